// round 6
// baseline (speedup 1.0000x reference)
#include <cuda_runtime.h>
#include <cuda_bf16.h>
#include <math.h>

#define FULLMASK 0xFFFFFFFFu
#define NW 4              // warps per block, one matrix per warp
#define BITERS 16         // bisection iterations

__device__ double g_acc = 0.0;
__device__ unsigned int g_cnt = 0;

// packed-triangular row offset: float4-aligned, gap(i)=i+4 rounded down >= i+1
__host__ __device__ constexpr int ro(int i) {
    return (i * (i + 1) / 2 + 3 * i + 3) & ~3;
}
#define LP_SIZE 640   // ro(31)=592, +31 data +3 overread pad -> 626, round up

__device__ __forceinline__ float warp_sum(float v) {
    v += __shfl_xor_sync(FULLMASK, v, 16);
    v += __shfl_xor_sync(FULLMASK, v, 8);
    v += __shfl_xor_sync(FULLMASK, v, 4);
    v += __shfl_xor_sync(FULLMASK, v, 2);
    v += __shfl_xor_sync(FULLMASK, v, 1);
    return v;
}

// raw approximate reciprocal: sign-correct (+-0 -> +-inf). Sturm needs signs only.
__device__ __forceinline__ float frcp(float x) {
    float r; asm("rcp.approx.f32 %0, %1;" : "=f"(r) : "f"(x)); return r;
}

__global__ __launch_bounds__(NW * 32, 7)
void rdl_main(const float* __restrict__ X, const float* __restrict__ Y,
              float* __restrict__ out, int B) {
    const int lane = threadIdx.x & 31;
    const int wid  = threadIdx.x >> 5;
    const int mat  = blockIdx.x * NW + wid;

    // Lp: packed lower-tri L (diag = 1/L[k][k]); reused for d/ds/e2/e after solves.
    __shared__ float Lp[NW][LP_SIZE];
    __shared__ float Bs[NW][32][33];   // transpose buffer; rows 0,4-5 reused for v / vw
    __shared__ float wsum[NW];

    float* lp = Lp[wid];
    float contrib = 0.0f;

    if (mat < B) {
        const float* xb = X + (size_t)mat * 1024;
        const float* yb = Y + (size_t)mat * 1024;

        // ---- load Y column `lane` (== row, symmetric) ----
        float Lr[32];
        #pragma unroll
        for (int c = 0; c < 32; ++c) Lr[c] = yb[c * 32 + lane];

        // packed write offset for this lane's row
        const int rl = ((lane * (lane + 1)) / 2 + 3 * lane + 3) & ~3;

        // ---- Cholesky: row k of L broadcast from packed smem as float4 ----
        #pragma unroll
        for (int k = 0; k < 32; ++k) {
            __syncwarp();
            float s0 = Lr[k], s1 = 0.f, s2 = 0.f, s3 = 0.f;
            #pragma unroll
            for (int g = 0; g * 4 < k; ++g) {
                float4 Lv = *(const float4*)(lp + ro(k) + g * 4);
                if (g*4+0 < k) s0 = fmaf(-Lr[g*4+0], Lv.x, s0);
                if (g*4+1 < k) s1 = fmaf(-Lr[g*4+1], Lv.y, s1);
                if (g*4+2 < k) s2 = fmaf(-Lr[g*4+2], Lv.z, s2);
                if (g*4+3 < k) s3 = fmaf(-Lr[g*4+3], Lv.w, s3);
            }
            float s   = (s0 + s1) + (s2 + s3);
            float skk = __shfl_sync(FULLMASK, s, k);
            float inv = rsqrtf(skk);
            float val = (lane == k) ? inv : s * inv;
            Lr[k] = val;
            if (lane >= k) lp[rl + k] = val;   // packed column store
        }
        __syncwarp();

        // ---- load X; forward solve L Z = X (thread = column) ----
        float z[32];
        #pragma unroll
        for (int c = 0; c < 32; ++c) z[c] = xb[c * 32 + lane];
        #pragma unroll
        for (int i = 0; i < 32; ++i) {
            float s = z[i];
            #pragma unroll
            for (int g = 0; g * 4 <= i; ++g) {
                float4 Lv = *(const float4*)(lp + ro(i) + g * 4);
                if (g*4+0 < i) s = fmaf(-Lv.x, z[g*4+0], s); else if (g*4+0 == i) s *= Lv.x;
                if (g*4+1 < i) s = fmaf(-Lv.y, z[g*4+1], s); else if (g*4+1 == i) s *= Lv.y;
                if (g*4+2 < i) s = fmaf(-Lv.z, z[g*4+2], s); else if (g*4+2 == i) s *= Lv.z;
                if (g*4+3 < i) s = fmaf(-Lv.w, z[g*4+3], s); else if (g*4+3 == i) s *= Lv.w;
            }
            z[i] = s;
        }

        // ---- transpose Z ----
        #pragma unroll
        for (int i = 0; i < 32; ++i) Bs[wid][lane][i] = z[i];
        __syncwarp();

        // ---- forward solve L M = Z^T  ->  M = L^{-1} X L^{-T} ----
        float m[32];
        #pragma unroll
        for (int i = 0; i < 32; ++i) {
            float s = Bs[wid][i][lane];
            #pragma unroll
            for (int g = 0; g * 4 <= i; ++g) {
                float4 Lv = *(const float4*)(lp + ro(i) + g * 4);
                if (g*4+0 < i) s = fmaf(-Lv.x, m[g*4+0], s); else if (g*4+0 == i) s *= Lv.x;
                if (g*4+1 < i) s = fmaf(-Lv.y, m[g*4+1], s); else if (g*4+1 == i) s *= Lv.y;
                if (g*4+2 < i) s = fmaf(-Lv.z, m[g*4+2], s); else if (g*4+2 == i) s *= Lv.z;
                if (g*4+3 < i) s = fmaf(-Lv.w, m[g*4+3], s); else if (g*4+3 == i) s *= Lv.w;
            }
            m[i] = s;
        }
        __syncwarp();   // Lp dead as L from here on -> reuse for d/ds/e2/e

        float* d_sh  = lp;        // [32] diag
        float* ds_sh = lp + 32;   // [32] diag shifted by 1 (d[i] at ds[i-1])
        float* e2_sh = lp + 64;   // [32] off-diag squared
        float* e_sh  = lp + 96;   // [32] off-diag

        // ---- Householder tridiag, range-limited trailing update ----
        float*  v_sh = &Bs[wid][0][0];            // 16B aligned
        float2* vw   = (float2*)&Bs[wid][4][0];   // 16B aligned
        #pragma unroll
        for (int k = 0; k < 30; ++k) {
            float xk    = (lane > k) ? m[k] : 0.0f;
            float alpha = __shfl_sync(FULLMASK, m[k], k + 1);
            float sigma = warp_sum((lane > k + 1) ? xk * xk : 0.0f);

            float mu    = sqrtf(fmaf(alpha, alpha, sigma));
            float beta  = (alpha >= 0.0f) ? -mu : mu;
            float tau   = __fdividef(beta - alpha, beta);
            float scale = __fdividef(1.0f, alpha - beta);
            float v     = (lane == k + 1) ? 1.0f
                        : ((lane > k + 1) ? xk * scale : 0.0f);
            if (sigma <= 1e-12f) { beta = alpha; tau = 0.0f; v = 0.0f; }  // warp-uniform
            if (lane == k) { d_sh[k] = m[k]; e_sh[k] = beta; }  // row k final
            v_sh[lane] = v;
            __syncwarp();

            // p = tau * A v  (v_j == 0 for j <= k -> float4 over-read exact)
            float p0 = 0.f, p1 = 0.f, p2 = 0.f, p3 = 0.f;
            #pragma unroll
            for (int g = (k + 1) & ~3; g < 32; g += 4) {
                float4 vv = *(const float4*)&v_sh[g];
                p0 = fmaf(m[g+0], vv.x, p0);
                p1 = fmaf(m[g+1], vv.y, p1);
                p2 = fmaf(m[g+2], vv.z, p2);
                p3 = fmaf(m[g+3], vv.w, p3);
            }
            float p = ((p0 + p1) + (p2 + p3)) * tau;

            float dot = tau * warp_sum(p * v);
            float w   = fmaf(-0.5f * dot, v, p);
            vw[lane]  = make_float2(v, w);
            __syncwarp();

            // trailing update: A <- A - v w^T - w v^T  (2 columns per LDS.128)
            #pragma unroll
            for (int g = (k + 1) & ~1; g < 32; g += 2) {
                float4 t = *(const float4*)&vw[g];     // {v_g, w_g, v_g1, w_g1}
                m[g+0] = fmaf(-v, t.y, fmaf(-w, t.x, m[g+0]));
                m[g+1] = fmaf(-v, t.w, fmaf(-w, t.z, m[g+1]));
            }
        }
        if (lane == 30) { d_sh[30] = m[30]; e_sh[30] = m[31]; }  // e[30]=M[31][30]
        if (lane == 31) { d_sh[31] = m[31]; }
        __syncwarp();

        // ---- build shifted/squared arrays + per-lane Gershgorin, reduce ----
        float d_l = d_sh[lane];
        float ev  = (lane < 31) ? e_sh[lane] : 0.f;
        if (lane >= 1) ds_sh[lane - 1] = d_l;
        if (lane < 31) e2_sh[lane] = fmaxf(ev * ev, 1e-28f);
        float em  = (lane > 0) ? e_sh[lane - 1] : 0.f;
        float r   = fabsf(em) + fabsf(ev);
        float gl  = d_l - r, gh = d_l + r;
        #pragma unroll
        for (int o = 16; o > 0; o >>= 1) {
            gl = fminf(gl, __shfl_xor_sync(FULLMASK, gl, o));
            gh = fmaxf(gh, __shfl_xor_sync(FULLMASK, gh, o));
        }
        float span = gh - gl;
        float lo = gl - 1e-4f * span - 1e-6f;
        float hi = gh + 1e-4f * span + 1e-6f;
        float d0 = __shfl_sync(FULLMASK, d_l, 0);
        __syncwarp();

        // ---- Sturm bisection: lane j isolates j-th smallest eigenvalue.
        //      d/e2 streamed from smem as float4 broadcasts (regs stay low). ----
        #pragma unroll 1
        for (int it = 0; it < BITERS; ++it) {
            float mid = 0.5f * (lo + hi);
            float q   = d0 - mid;
            int   c   = __float_as_int(q) >> 31;      // -1 per negative pivot
            #pragma unroll
            for (int g = 0; g < 8; ++g) {             // i = 4g+1 .. 4g+4 (last: ..31)
                float4 dd = *(const float4*)&ds_sh[g * 4];
                float4 ee = *(const float4*)&e2_sh[g * 4];
                q = fmaf(-ee.x, frcp(q), dd.x - mid); c += __float_as_int(q) >> 31;
                q = fmaf(-ee.y, frcp(q), dd.y - mid); c += __float_as_int(q) >> 31;
                q = fmaf(-ee.z, frcp(q), dd.z - mid); c += __float_as_int(q) >> 31;
                if (g < 7) {
                    q = fmaf(-ee.w, frcp(q), dd.w - mid); c += __float_as_int(q) >> 31;
                }
            }
            bool up = (c + lane >= 0);                // count(<mid) <= lane
            lo = up ? mid : lo;
            hi = up ? hi  : mid;
        }
        float lam = fmaxf(0.5f * (lo + hi), 1e-20f);
        float lg  = logf(lam);
        contrib   = sqrtf(warp_sum(lg * lg));
    }

    // ---- block reduce + last-block finalize ----
    if (lane == 0) wsum[wid] = contrib;
    __syncthreads();
    if (threadIdx.x == 0) {
        double s = ((double)wsum[0] + (double)wsum[1])
                 + ((double)wsum[2] + (double)wsum[3]);
        atomicAdd(&g_acc, s);
        __threadfence();
        unsigned t = atomicAdd(&g_cnt, 1u);
        if (t == gridDim.x - 1) {
            __threadfence();
            out[0] = (float)(g_acc / (double)B);
            g_acc = 0.0;
            g_cnt = 0u;
        }
    }
}

extern "C" void kernel_launch(void* const* d_in, const int* in_sizes, int n_in,
                              void* d_out, int out_size) {
    const float* x = (const float*)d_in[0];
    const float* y = (const float*)d_in[1];
    int B = in_sizes[0] / 1024;
    float* out = (float*)d_out;

    int blocks = (B + NW - 1) / NW;
    rdl_main<<<blocks, NW * 32>>>(x, y, out, B);
}

// round 7
// speedup vs baseline: 1.1791x; 1.1791x over previous
#include <cuda_runtime.h>
#include <cuda_bf16.h>
#include <math.h>

#define FULLMASK 0xFFFFFFFFu
#define NW 4              // warps per block, one matrix per warp
#define BITERS 12         // bisection iterations (error floor is fp32 output ulp)

__device__ double g_acc = 0.0;
__device__ unsigned int g_cnt = 0;

// packed-triangular row offset: float4-aligned, gap(i) >= i+1
__host__ __device__ constexpr int ro(int i) {
    return (i * (i + 1) / 2 + 3 * i + 3) & ~3;
}
#define LP_SIZE 640

__device__ __forceinline__ float warp_sum(float v) {
    v += __shfl_xor_sync(FULLMASK, v, 16);
    v += __shfl_xor_sync(FULLMASK, v, 8);
    v += __shfl_xor_sync(FULLMASK, v, 4);
    v += __shfl_xor_sync(FULLMASK, v, 2);
    v += __shfl_xor_sync(FULLMASK, v, 1);
    return v;
}

// raw approximate reciprocal: sign-correct (+-0 -> +-inf). Sturm needs signs only.
__device__ __forceinline__ float frcp(float x) {
    float r; asm("rcp.approx.f32 %0, %1;" : "=f"(r) : "f"(x)); return r;
}
__device__ __forceinline__ float fsqrt_ap(float x) {
    float r; asm("sqrt.approx.f32 %0, %1;" : "=f"(r) : "f"(x)); return r;
}

__global__ __launch_bounds__(NW * 32, 5)
void rdl_main(const float* __restrict__ X, const float* __restrict__ Y,
              float* __restrict__ out, int B) {
    const int lane = threadIdx.x & 31;
    const int wid  = threadIdx.x >> 5;
    const int mat  = blockIdx.x * NW + wid;

    // Lp: packed lower-tri L (diag = 1/L[k][k]); reused for d/e after the solves.
    __shared__ float Lp[NW][LP_SIZE];
    __shared__ float Bs[NW][32][33];   // transpose buffer; rows 0,4-5 reused for v / vw
    __shared__ float wsum[NW];

    float* lp = Lp[wid];
    float contrib = 0.0f;

    if (mat < B) {
        const float* xb = X + (size_t)mat * 1024;
        const float* yb = Y + (size_t)mat * 1024;

        // ---- load Y column `lane` (== row, symmetric) ----
        float Lr[32];
        #pragma unroll
        for (int c = 0; c < 32; ++c) Lr[c] = yb[c * 32 + lane];

        const int rl = ((lane * (lane + 1)) / 2 + 3 * lane + 3) & ~3;

        // ---- Cholesky: row k of L broadcast from packed smem as float4 ----
        #pragma unroll
        for (int k = 0; k < 32; ++k) {
            __syncwarp();
            float s0 = Lr[k], s1 = 0.f, s2 = 0.f, s3 = 0.f;
            #pragma unroll
            for (int g = 0; g * 4 < k; ++g) {
                float4 Lv = *(const float4*)(lp + ro(k) + g * 4);
                if (g*4+0 < k) s0 = fmaf(-Lr[g*4+0], Lv.x, s0);
                if (g*4+1 < k) s1 = fmaf(-Lr[g*4+1], Lv.y, s1);
                if (g*4+2 < k) s2 = fmaf(-Lr[g*4+2], Lv.z, s2);
                if (g*4+3 < k) s3 = fmaf(-Lr[g*4+3], Lv.w, s3);
            }
            float s   = (s0 + s1) + (s2 + s3);
            float skk = __shfl_sync(FULLMASK, s, k);
            float inv = rsqrtf(skk);
            float val = (lane == k) ? inv : s * inv;
            Lr[k] = val;
            if (lane >= k) lp[rl + k] = val;   // packed column store
        }
        __syncwarp();

        // ---- load X; forward solve L Z = X (thread = column) ----
        float z[32];
        #pragma unroll
        for (int c = 0; c < 32; ++c) z[c] = xb[c * 32 + lane];
        #pragma unroll
        for (int i = 0; i < 32; ++i) {
            float s = z[i];
            #pragma unroll
            for (int g = 0; g * 4 <= i; ++g) {
                float4 Lv = *(const float4*)(lp + ro(i) + g * 4);
                if (g*4+0 < i) s = fmaf(-Lv.x, z[g*4+0], s); else if (g*4+0 == i) s *= Lv.x;
                if (g*4+1 < i) s = fmaf(-Lv.y, z[g*4+1], s); else if (g*4+1 == i) s *= Lv.y;
                if (g*4+2 < i) s = fmaf(-Lv.z, z[g*4+2], s); else if (g*4+2 == i) s *= Lv.z;
                if (g*4+3 < i) s = fmaf(-Lv.w, z[g*4+3], s); else if (g*4+3 == i) s *= Lv.w;
            }
            z[i] = s;
        }

        // ---- transpose Z ----
        #pragma unroll
        for (int i = 0; i < 32; ++i) Bs[wid][lane][i] = z[i];
        __syncwarp();

        // ---- forward solve L M = Z^T  ->  M = L^{-1} X L^{-T} ----
        float m[32];
        #pragma unroll
        for (int i = 0; i < 32; ++i) {
            float s = Bs[wid][i][lane];
            #pragma unroll
            for (int g = 0; g * 4 <= i; ++g) {
                float4 Lv = *(const float4*)(lp + ro(i) + g * 4);
                if (g*4+0 < i) s = fmaf(-Lv.x, m[g*4+0], s); else if (g*4+0 == i) s *= Lv.x;
                if (g*4+1 < i) s = fmaf(-Lv.y, m[g*4+1], s); else if (g*4+1 == i) s *= Lv.y;
                if (g*4+2 < i) s = fmaf(-Lv.z, m[g*4+2], s); else if (g*4+2 == i) s *= Lv.z;
                if (g*4+3 < i) s = fmaf(-Lv.w, m[g*4+3], s); else if (g*4+3 == i) s *= Lv.w;
            }
            m[i] = s;
        }
        __syncwarp();   // Lp dead as L from here -> reuse for d / e

        float* d_sh = lp;        // [32] diag of T        (16B aligned)
        float* e_sh = lp + 32;   // [32] off-diag of T    (16B aligned)

        // ---- Householder tridiag, range-limited trailing update ----
        float*  v_sh = &Bs[wid][0][0];            // 16B aligned
        float2* vw   = (float2*)&Bs[wid][4][0];   // 16B aligned
        float e[31];                              // warp-uniform copy in registers
        #pragma unroll
        for (int k = 0; k < 30; ++k) {
            float xk    = (lane > k) ? m[k] : 0.0f;
            float alpha = __shfl_sync(FULLMASK, m[k], k + 1);
            float sigma = warp_sum((lane > k + 1) ? xk * xk : 0.0f);

            float mu    = fsqrt_ap(fmaf(alpha, alpha, sigma));
            float beta  = (alpha >= 0.0f) ? -mu : mu;
            float tau   = __fdividef(beta - alpha, beta);
            float scale = __fdividef(1.0f, alpha - beta);
            float v     = (lane == k + 1) ? 1.0f
                        : ((lane > k + 1) ? xk * scale : 0.0f);
            if (sigma <= 1e-12f) { beta = alpha; tau = 0.0f; v = 0.0f; }  // warp-uniform
            e[k] = beta;
            if (lane == k) { d_sh[k] = m[k]; e_sh[k] = beta; }  // row k final
            v_sh[lane] = v;
            __syncwarp();

            // p = tau * A v  (v_j == 0 for j <= k -> float4 over-read exact)
            float p0 = 0.f, p1 = 0.f, p2 = 0.f, p3 = 0.f;
            #pragma unroll
            for (int g = (k + 1) & ~3; g < 32; g += 4) {
                float4 vv = *(const float4*)&v_sh[g];
                p0 = fmaf(m[g+0], vv.x, p0);
                p1 = fmaf(m[g+1], vv.y, p1);
                p2 = fmaf(m[g+2], vv.z, p2);
                p3 = fmaf(m[g+3], vv.w, p3);
            }
            float p = ((p0 + p1) + (p2 + p3)) * tau;

            float dot = tau * warp_sum(p * v);
            float w   = fmaf(-0.5f * dot, v, p);
            vw[lane]  = make_float2(v, w);
            __syncwarp();

            // trailing update: A <- A - v w^T - w v^T  (2 columns per LDS.128)
            #pragma unroll
            for (int g = (k + 1) & ~1; g < 32; g += 2) {
                float4 t = *(const float4*)&vw[g];     // {v_g, w_g, v_g1, w_g1}
                m[g+0] = fmaf(-v, t.y, fmaf(-w, t.x, m[g+0]));
                m[g+1] = fmaf(-v, t.w, fmaf(-w, t.z, m[g+1]));
            }
        }
        e[30] = __shfl_sync(FULLMASK, m[31], 30);   // M[31][30] lives on lane 30
        if (lane == 30) { d_sh[30] = m[30]; e_sh[30] = m[31]; }
        if (lane == 31) { d_sh[31] = m[31]; }
        __syncwarp();

        // ---- Gershgorin: per-lane row radius, 10-shfl min/max reduce ----
        float d_l = d_sh[lane];
        float ev  = (lane < 31) ? e_sh[lane] : 0.f;
        float em  = (lane > 0)  ? e_sh[lane - 1] : 0.f;
        float r   = fabsf(em) + fabsf(ev);
        float gl  = d_l - r, gh = d_l + r;
        #pragma unroll
        for (int o = 16; o > 0; o >>= 1) {
            gl = fminf(gl, __shfl_xor_sync(FULLMASK, gl, o));
            gh = fmaxf(gh, __shfl_xor_sync(FULLMASK, gh, o));
        }
        float span = gh - gl;
        float lo = gl - 1e-4f * span - 1e-6f;
        float hi = gh + 1e-4f * span + 1e-6f;

        // ---- pull T into registers: d via 8 float4 broadcasts, e2 from reg e ----
        float d[32], e2[31];
        #pragma unroll
        for (int g = 0; g < 8; ++g) {
            float4 dd = *(const float4*)&d_sh[g * 4];
            d[g*4+0] = dd.x; d[g*4+1] = dd.y; d[g*4+2] = dd.z; d[g*4+3] = dd.w;
        }
        #pragma unroll
        for (int i = 0; i < 31; ++i) e2[i] = fmaxf(e[i] * e[i], 1e-28f);

        // ---- Sturm bisection: lane j isolates the j-th smallest eigenvalue ----
        #pragma unroll 1
        for (int it = 0; it < BITERS; ++it) {
            float mid = 0.5f * (lo + hi);
            float q   = d[0] - mid;
            int   c   = __float_as_int(q) >> 31;      // -1 per negative pivot
            #pragma unroll
            for (int i = 1; i < 32; ++i) {
                q  = fmaf(-e2[i - 1], frcp(q), d[i] - mid);
                c += __float_as_int(q) >> 31;
            }
            bool up = (c + lane >= 0);                // count(<mid) <= lane
            lo = up ? mid : lo;
            hi = up ? hi  : mid;
        }
        float lam = fmaxf(0.5f * (lo + hi), 1e-20f);
        float lg  = __logf(lam);
        contrib   = fsqrt_ap(warp_sum(lg * lg));
    }

    // ---- block reduce + last-block finalize ----
    if (lane == 0) wsum[wid] = contrib;
    __syncthreads();
    if (threadIdx.x == 0) {
        double s = ((double)wsum[0] + (double)wsum[1])
                 + ((double)wsum[2] + (double)wsum[3]);
        atomicAdd(&g_acc, s);
        __threadfence();
        unsigned t = atomicAdd(&g_cnt, 1u);
        if (t == gridDim.x - 1) {
            __threadfence();
            out[0] = (float)(g_acc / (double)B);
            g_acc = 0.0;
            g_cnt = 0u;
        }
    }
}

extern "C" void kernel_launch(void* const* d_in, const int* in_sizes, int n_in,
                              void* d_out, int out_size) {
    const float* x = (const float*)d_in[0];
    const float* y = (const float*)d_in[1];
    int B = in_sizes[0] / 1024;
    float* out = (float*)d_out;

    int blocks = (B + NW - 1) / NW;
    rdl_main<<<blocks, NW * 32>>>(x, y, out, B);
}

// round 8
// speedup vs baseline: 1.2782x; 1.0840x over previous
#include <cuda_runtime.h>
#include <cuda_bf16.h>
#include <math.h>

#define FULLMASK 0xFFFFFFFFu
#define NW 4              // warps per block, one matrix per warp
#define BITERS 10         // bisection iterations (err ~2e-6 << 1e-3 threshold)

// Compiler-only ordering fence for same-warp cross-lane smem traffic.
// Valid here because every STS->LDS pair sits in CONVERGED control flow
// (all branches warp-uniform or predicated): in-order issue + in-order MIO
// drain give the hardware ordering; this stops NVVM/ptxas reordering.
#define WFENCE() asm volatile("" ::: "memory")

__device__ double g_acc = 0.0;
__device__ unsigned int g_cnt = 0;

// packed-triangular row offset: float4-aligned, gap(i) >= i+1
__host__ __device__ constexpr int ro(int i) {
    return (i * (i + 1) / 2 + 3 * i + 3) & ~3;
}
#define LP_SIZE 640

__device__ __forceinline__ float warp_sum(float v) {
    v += __shfl_xor_sync(FULLMASK, v, 16);
    v += __shfl_xor_sync(FULLMASK, v, 8);
    v += __shfl_xor_sync(FULLMASK, v, 4);
    v += __shfl_xor_sync(FULLMASK, v, 2);
    v += __shfl_xor_sync(FULLMASK, v, 1);
    return v;
}

// raw approximate reciprocal: sign-correct (+-0 -> +-inf). Sturm needs signs only.
__device__ __forceinline__ float frcp(float x) {
    float r; asm("rcp.approx.f32 %0, %1;" : "=f"(r) : "f"(x)); return r;
}
__device__ __forceinline__ float fsqrt_ap(float x) {
    float r; asm("sqrt.approx.f32 %0, %1;" : "=f"(r) : "f"(x)); return r;
}

__global__ __launch_bounds__(NW * 32, 5)
void rdl_main(const float* __restrict__ X, const float* __restrict__ Y,
              float* __restrict__ out, int B) {
    const int lane = threadIdx.x & 31;
    const int wid  = threadIdx.x >> 5;
    const int mat  = blockIdx.x * NW + wid;

    // Lp: packed lower-tri L (diag = 1/L[k][k]); reused for d/e after the solves.
    __shared__ float Lp[NW][LP_SIZE];
    __shared__ float Bs[NW][32][33];   // transpose buffer; rows 0,4-5 reused for v / vw
    __shared__ float wsum[NW];

    float* lp = Lp[wid];
    float contrib = 0.0f;

    if (mat < B) {                     // warp-uniform branch (mat is per-warp)
        const float* xb = X + (size_t)mat * 1024;
        const float* yb = Y + (size_t)mat * 1024;

        // ---- load Y column `lane` (== row, symmetric) ----
        float Lr[32];
        #pragma unroll
        for (int c = 0; c < 32; ++c) Lr[c] = yb[c * 32 + lane];

        const int rl = ((lane * (lane + 1)) / 2 + 3 * lane + 3) & ~3;

        // ---- Cholesky: row k of L broadcast from packed smem as float4 ----
        #pragma unroll
        for (int k = 0; k < 32; ++k) {
            WFENCE();
            float s0 = Lr[k], s1 = 0.f, s2 = 0.f, s3 = 0.f;
            #pragma unroll
            for (int g = 0; g * 4 < k; ++g) {
                float4 Lv = *(const float4*)(lp + ro(k) + g * 4);
                if (g*4+0 < k) s0 = fmaf(-Lr[g*4+0], Lv.x, s0);
                if (g*4+1 < k) s1 = fmaf(-Lr[g*4+1], Lv.y, s1);
                if (g*4+2 < k) s2 = fmaf(-Lr[g*4+2], Lv.z, s2);
                if (g*4+3 < k) s3 = fmaf(-Lr[g*4+3], Lv.w, s3);
            }
            float s   = (s0 + s1) + (s2 + s3);
            float skk = __shfl_sync(FULLMASK, s, k);
            float inv = rsqrtf(skk);
            float val = (lane == k) ? inv : s * inv;
            Lr[k] = val;
            if (lane >= k) lp[rl + k] = val;   // predicated packed column store
        }
        WFENCE();

        // ---- load X; forward solve L Z = X (thread = column) ----
        float z[32];
        #pragma unroll
        for (int c = 0; c < 32; ++c) z[c] = xb[c * 32 + lane];
        #pragma unroll
        for (int i = 0; i < 32; ++i) {
            float s = z[i];
            #pragma unroll
            for (int g = 0; g * 4 <= i; ++g) {
                float4 Lv = *(const float4*)(lp + ro(i) + g * 4);
                if (g*4+0 < i) s = fmaf(-Lv.x, z[g*4+0], s); else if (g*4+0 == i) s *= Lv.x;
                if (g*4+1 < i) s = fmaf(-Lv.y, z[g*4+1], s); else if (g*4+1 == i) s *= Lv.y;
                if (g*4+2 < i) s = fmaf(-Lv.z, z[g*4+2], s); else if (g*4+2 == i) s *= Lv.z;
                if (g*4+3 < i) s = fmaf(-Lv.w, z[g*4+3], s); else if (g*4+3 == i) s *= Lv.w;
            }
            z[i] = s;
        }

        // ---- transpose Z ----
        #pragma unroll
        for (int i = 0; i < 32; ++i) Bs[wid][lane][i] = z[i];
        WFENCE();

        // ---- forward solve L M = Z^T  ->  M = L^{-1} X L^{-T} ----
        float m[32];
        #pragma unroll
        for (int i = 0; i < 32; ++i) {
            float s = Bs[wid][i][lane];
            #pragma unroll
            for (int g = 0; g * 4 <= i; ++g) {
                float4 Lv = *(const float4*)(lp + ro(i) + g * 4);
                if (g*4+0 < i) s = fmaf(-Lv.x, m[g*4+0], s); else if (g*4+0 == i) s *= Lv.x;
                if (g*4+1 < i) s = fmaf(-Lv.y, m[g*4+1], s); else if (g*4+1 == i) s *= Lv.y;
                if (g*4+2 < i) s = fmaf(-Lv.z, m[g*4+2], s); else if (g*4+2 == i) s *= Lv.z;
                if (g*4+3 < i) s = fmaf(-Lv.w, m[g*4+3], s); else if (g*4+3 == i) s *= Lv.w;
            }
            m[i] = s;
        }
        WFENCE();   // Lp dead as L from here -> reuse for d / e

        float* d_sh = lp;        // [32] diag of T        (16B aligned)
        float* e_sh = lp + 32;   // [32] off-diag of T    (16B aligned)

        // ---- Householder tridiag, range-limited trailing update ----
        float*  v_sh = &Bs[wid][0][0];            // 16B aligned
        float2* vw   = (float2*)&Bs[wid][4][0];   // 16B aligned
        float e[31];                              // warp-uniform copy in registers
        #pragma unroll
        for (int k = 0; k < 30; ++k) {
            float xk    = (lane > k) ? m[k] : 0.0f;
            float alpha = __shfl_sync(FULLMASK, m[k], k + 1);
            float sigma = warp_sum((lane > k + 1) ? xk * xk : 0.0f);

            float mu    = fsqrt_ap(fmaf(alpha, alpha, sigma));
            float beta  = (alpha >= 0.0f) ? -mu : mu;
            float tau   = __fdividef(beta - alpha, beta);
            float scale = __fdividef(1.0f, alpha - beta);
            float v     = (lane == k + 1) ? 1.0f
                        : ((lane > k + 1) ? xk * scale : 0.0f);
            if (sigma <= 1e-12f) { beta = alpha; tau = 0.0f; v = 0.0f; }  // warp-uniform
            e[k] = beta;
            if (lane == k) { d_sh[k] = m[k]; e_sh[k] = beta; }  // row k final
            v_sh[lane] = v;
            WFENCE();

            // p = tau * A v  (v_j == 0 for j <= k -> float4 over-read exact)
            float p0 = 0.f, p1 = 0.f, p2 = 0.f, p3 = 0.f;
            #pragma unroll
            for (int g = (k + 1) & ~3; g < 32; g += 4) {
                float4 vv = *(const float4*)&v_sh[g];
                p0 = fmaf(m[g+0], vv.x, p0);
                p1 = fmaf(m[g+1], vv.y, p1);
                p2 = fmaf(m[g+2], vv.z, p2);
                p3 = fmaf(m[g+3], vv.w, p3);
            }
            float p = ((p0 + p1) + (p2 + p3)) * tau;

            float dot = tau * warp_sum(p * v);
            float w   = fmaf(-0.5f * dot, v, p);
            vw[lane]  = make_float2(v, w);
            WFENCE();

            // trailing update: A <- A - v w^T - w v^T  (2 columns per LDS.128)
            #pragma unroll
            for (int g = (k + 1) & ~1; g < 32; g += 2) {
                float4 t = *(const float4*)&vw[g];     // {v_g, w_g, v_g1, w_g1}
                m[g+0] = fmaf(-v, t.y, fmaf(-w, t.x, m[g+0]));
                m[g+1] = fmaf(-v, t.w, fmaf(-w, t.z, m[g+1]));
            }
        }
        e[30] = __shfl_sync(FULLMASK, m[31], 30);   // M[31][30] lives on lane 30
        if (lane == 30) { d_sh[30] = m[30]; e_sh[30] = m[31]; }
        if (lane == 31) { d_sh[31] = m[31]; }
        WFENCE();

        // ---- Gershgorin: per-lane row radius, 10-shfl min/max reduce ----
        float d_l = d_sh[lane];
        float ev  = (lane < 31) ? e_sh[lane] : 0.f;
        float em  = (lane > 0)  ? e_sh[lane - 1] : 0.f;
        float r   = fabsf(em) + fabsf(ev);
        float gl  = d_l - r, gh = d_l + r;
        #pragma unroll
        for (int o = 16; o > 0; o >>= 1) {
            gl = fminf(gl, __shfl_xor_sync(FULLMASK, gl, o));
            gh = fmaxf(gh, __shfl_xor_sync(FULLMASK, gh, o));
        }
        float span = gh - gl;
        float lo = gl - 1e-4f * span - 1e-6f;
        float hi = gh + 1e-4f * span + 1e-6f;

        // ---- pull T into registers: d via 8 float4 broadcasts, e2 from reg e ----
        float d[32], e2[31];
        #pragma unroll
        for (int g = 0; g < 8; ++g) {
            float4 dd = *(const float4*)&d_sh[g * 4];
            d[g*4+0] = dd.x; d[g*4+1] = dd.y; d[g*4+2] = dd.z; d[g*4+3] = dd.w;
        }
        #pragma unroll
        for (int i = 0; i < 31; ++i) e2[i] = fmaxf(e[i] * e[i], 1e-28f);

        // ---- Sturm bisection: lane j isolates the j-th smallest eigenvalue ----
        #pragma unroll 1
        for (int it = 0; it < BITERS; ++it) {
            float mid = 0.5f * (lo + hi);
            float q   = d[0] - mid;
            int   c   = __float_as_int(q) >> 31;      // -1 per negative pivot
            #pragma unroll
            for (int i = 1; i < 32; ++i) {
                q  = fmaf(-e2[i - 1], frcp(q), d[i] - mid);
                c += __float_as_int(q) >> 31;
            }
            bool up = (c + lane >= 0);                // count(<mid) <= lane
            lo = up ? mid : lo;
            hi = up ? hi  : mid;
        }
        float lam = fmaxf(0.5f * (lo + hi), 1e-20f);
        float lg  = __logf(lam);
        contrib   = fsqrt_ap(warp_sum(lg * lg));
    }

    // ---- block reduce + last-block finalize ----
    if (lane == 0) wsum[wid] = contrib;
    __syncthreads();
    if (threadIdx.x == 0) {
        double s = ((double)wsum[0] + (double)wsum[1])
                 + ((double)wsum[2] + (double)wsum[3]);
        atomicAdd(&g_acc, s);
        __threadfence();
        unsigned t = atomicAdd(&g_cnt, 1u);
        if (t == gridDim.x - 1) {
            __threadfence();
            out[0] = (float)(g_acc / (double)B);
            g_acc = 0.0;
            g_cnt = 0u;
        }
    }
}

extern "C" void kernel_launch(void* const* d_in, const int* in_sizes, int n_in,
                              void* d_out, int out_size) {
    const float* x = (const float*)d_in[0];
    const float* y = (const float*)d_in[1];
    int B = in_sizes[0] / 1024;
    float* out = (float*)d_out;

    int blocks = (B + NW - 1) / NW;
    rdl_main<<<blocks, NW * 32>>>(x, y, out, B);
}

// round 9
// speedup vs baseline: 1.4198x; 1.1108x over previous
#include <cuda_runtime.h>
#include <cuda_bf16.h>
#include <math.h>

#define FULLMASK 0xFFFFFFFFu
#define NW 4              // warps per block, one matrix per warp
#define BITERS 8          // bisection iterations (err ~8e-5 << 1e-3 threshold)

// Compiler-only ordering fence for same-warp cross-lane smem traffic
// (all STS->LDS pairs sit in converged control flow; hardware order is
// in-order issue + in-order MIO drain, so only compiler reordering must stop).
#define WFENCE() asm volatile("" ::: "memory")

__device__ double g_acc = 0.0;
__device__ unsigned int g_cnt = 0;

// packed-triangular row offset: float4-aligned, gap(i) >= i+1
__host__ __device__ constexpr int ro(int i) {
    return (i * (i + 1) / 2 + 3 * i + 3) & ~3;
}
#define LP_SIZE 640

__device__ __forceinline__ float warp_sum(float v) {
    v += __shfl_xor_sync(FULLMASK, v, 16);
    v += __shfl_xor_sync(FULLMASK, v, 8);
    v += __shfl_xor_sync(FULLMASK, v, 4);
    v += __shfl_xor_sync(FULLMASK, v, 2);
    v += __shfl_xor_sync(FULLMASK, v, 1);
    return v;
}

// raw approximate reciprocal: sign-correct (+-0 -> +-inf). Sturm needs signs only.
__device__ __forceinline__ float frcp(float x) {
    float r; asm("rcp.approx.f32 %0, %1;" : "=f"(r) : "f"(x)); return r;
}
__device__ __forceinline__ float fsqrt_ap(float x) {
    float r; asm("sqrt.approx.f32 %0, %1;" : "=f"(r) : "f"(x)); return r;
}

__global__ __launch_bounds__(NW * 32, 6)
void rdl_main(const float* __restrict__ X, const float* __restrict__ Y,
              float* __restrict__ out, int B) {
    const int lane = threadIdx.x & 31;
    const int wid  = threadIdx.x >> 5;
    const int mat  = blockIdx.x * NW + wid;

    // Lp: packed lower-tri L (diag = 1/L[k][k]); reused for d/e after the solves.
    __shared__ float Lp[NW][LP_SIZE];
    __shared__ float Bs[NW][32][33];   // transpose buffer; rows 0,4-5 reused for u / uw
    __shared__ float wsum[NW];

    float* lp = Lp[wid];
    float contrib = 0.0f;

    if (mat < B) {                     // warp-uniform branch (mat is per-warp)
        const float* xb = X + (size_t)mat * 1024;
        const float* yb = Y + (size_t)mat * 1024;

        // ---- load Y column `lane` (== row, symmetric) ----
        float Lr[32];
        #pragma unroll
        for (int c = 0; c < 32; ++c) Lr[c] = yb[c * 32 + lane];

        const int rl = ((lane * (lane + 1)) / 2 + 3 * lane + 3) & ~3;

        // ---- Cholesky: row k of L broadcast from packed smem as float4 ----
        #pragma unroll
        for (int k = 0; k < 32; ++k) {
            WFENCE();
            float s0 = Lr[k], s1 = 0.f, s2 = 0.f, s3 = 0.f;
            #pragma unroll
            for (int g = 0; g * 4 < k; ++g) {
                float4 Lv = *(const float4*)(lp + ro(k) + g * 4);
                if (g*4+0 < k) s0 = fmaf(-Lr[g*4+0], Lv.x, s0);
                if (g*4+1 < k) s1 = fmaf(-Lr[g*4+1], Lv.y, s1);
                if (g*4+2 < k) s2 = fmaf(-Lr[g*4+2], Lv.z, s2);
                if (g*4+3 < k) s3 = fmaf(-Lr[g*4+3], Lv.w, s3);
            }
            float s   = (s0 + s1) + (s2 + s3);
            float skk = __shfl_sync(FULLMASK, s, k);
            float inv = rsqrtf(skk);
            float val = (lane == k) ? inv : s * inv;
            Lr[k] = val;
            if (lane >= k) lp[rl + k] = val;   // predicated packed column store
        }
        WFENCE();

        // ---- load X; forward solve L Z = X (thread = column) ----
        float z[32];
        #pragma unroll
        for (int c = 0; c < 32; ++c) z[c] = xb[c * 32 + lane];
        #pragma unroll
        for (int i = 0; i < 32; ++i) {
            float s = z[i];
            #pragma unroll
            for (int g = 0; g * 4 <= i; ++g) {
                float4 Lv = *(const float4*)(lp + ro(i) + g * 4);
                if (g*4+0 < i) s = fmaf(-Lv.x, z[g*4+0], s); else if (g*4+0 == i) s *= Lv.x;
                if (g*4+1 < i) s = fmaf(-Lv.y, z[g*4+1], s); else if (g*4+1 == i) s *= Lv.y;
                if (g*4+2 < i) s = fmaf(-Lv.z, z[g*4+2], s); else if (g*4+2 == i) s *= Lv.z;
                if (g*4+3 < i) s = fmaf(-Lv.w, z[g*4+3], s); else if (g*4+3 == i) s *= Lv.w;
            }
            z[i] = s;
        }

        // ---- transpose Z ----
        #pragma unroll
        for (int i = 0; i < 32; ++i) Bs[wid][lane][i] = z[i];
        WFENCE();

        // ---- forward solve L M = Z^T  ->  M = L^{-1} X L^{-T} ----
        float m[32];
        #pragma unroll
        for (int i = 0; i < 32; ++i) {
            float s = Bs[wid][i][lane];
            #pragma unroll
            for (int g = 0; g * 4 <= i; ++g) {
                float4 Lv = *(const float4*)(lp + ro(i) + g * 4);
                if (g*4+0 < i) s = fmaf(-Lv.x, m[g*4+0], s); else if (g*4+0 == i) s *= Lv.x;
                if (g*4+1 < i) s = fmaf(-Lv.y, m[g*4+1], s); else if (g*4+1 == i) s *= Lv.y;
                if (g*4+2 < i) s = fmaf(-Lv.z, m[g*4+2], s); else if (g*4+2 == i) s *= Lv.z;
                if (g*4+3 < i) s = fmaf(-Lv.w, m[g*4+3], s); else if (g*4+3 == i) s *= Lv.w;
            }
            m[i] = s;
        }
        WFENCE();   // Lp dead as L from here -> reuse for d / e

        float* d_sh = lp;        // [32] diag of T        (16B aligned)
        float* e_sh = lp + 32;   // [32] off-diag of T    (16B aligned)

        // ---- Householder tridiag with UNNORMALIZED reflector u = x - beta*e1:
        //      H = I - tau u u^T, tau = 2/||u||^2. One division per step. ----
        float*  u_sh = &Bs[wid][0][0];            // 16B aligned
        float2* uw   = (float2*)&Bs[wid][4][0];   // 16B aligned
        #pragma unroll
        for (int k = 0; k < 30; ++k) {
            float xk    = (lane > k) ? m[k] : 0.0f;
            float alpha = __shfl_sync(FULLMASK, m[k], k + 1);
            float sigma = warp_sum((lane > k + 1) ? xk * xk : 0.0f);

            float mu    = fsqrt_ap(fmaf(alpha, alpha, sigma));
            float beta  = (alpha >= 0.0f) ? -mu : mu;
            float ab    = alpha - beta;
            float tau   = __fdividef(2.0f, fmaf(ab, ab, sigma));  // 2/||u||^2
            float u     = (lane == k + 1) ? ab : xk;              // xk==0 for lane<=k
            if (sigma <= 1e-12f) { beta = alpha; tau = 0.0f; u = 0.0f; }  // warp-uniform
            if (lane == k) { d_sh[k] = m[k]; e_sh[k] = beta; }    // row k final
            u_sh[lane] = u;
            WFENCE();

            // p = tau * A u  (u_j == 0 for j <= k -> float4 over-read exact)
            float p0 = 0.f, p1 = 0.f, p2 = 0.f, p3 = 0.f;
            #pragma unroll
            for (int g = (k + 1) & ~3; g < 32; g += 4) {
                float4 uu = *(const float4*)&u_sh[g];
                p0 = fmaf(m[g+0], uu.x, p0);
                p1 = fmaf(m[g+1], uu.y, p1);
                p2 = fmaf(m[g+2], uu.z, p2);
                p3 = fmaf(m[g+3], uu.w, p3);
            }
            float p = ((p0 + p1) + (p2 + p3)) * tau;

            float dot = tau * warp_sum(p * u);
            float w   = fmaf(-0.5f * dot, u, p);
            uw[lane]  = make_float2(u, w);
            WFENCE();

            // trailing update: A <- A - u w^T - w u^T  (2 columns per LDS.128)
            #pragma unroll
            for (int g = (k + 1) & ~1; g < 32; g += 2) {
                float4 t = *(const float4*)&uw[g];     // {u_g, w_g, u_g1, w_g1}
                m[g+0] = fmaf(-u, t.y, fmaf(-w, t.x, m[g+0]));
                m[g+1] = fmaf(-u, t.w, fmaf(-w, t.z, m[g+1]));
            }
        }
        if (lane == 30) { d_sh[30] = m[30]; e_sh[30] = m[31]; }  // e[30]=M[31][30]
        if (lane == 31) { d_sh[31] = m[31]; e_sh[31] = 0.0f; }
        WFENCE();

        // ---- Gershgorin: per-lane row radius, 10-shfl min/max reduce ----
        float d_l = d_sh[lane];
        float ev  = (lane < 31) ? e_sh[lane] : 0.f;
        float em  = (lane > 0)  ? e_sh[lane - 1] : 0.f;
        float r   = fabsf(em) + fabsf(ev);
        float gl  = d_l - r, gh = d_l + r;
        #pragma unroll
        for (int o = 16; o > 0; o >>= 1) {
            gl = fminf(gl, __shfl_xor_sync(FULLMASK, gl, o));
            gh = fmaxf(gh, __shfl_xor_sync(FULLMASK, gh, o));
        }
        float span = gh - gl;
        float lo = gl - 1e-4f * span - 1e-6f;
        float hi = gh + 1e-4f * span + 1e-6f;

        // ---- pull T into registers: d and e via one-time float4 broadcasts ----
        float d[32], e2[31];
        #pragma unroll
        for (int g = 0; g < 8; ++g) {
            float4 dd = *(const float4*)&d_sh[g * 4];
            d[g*4+0] = dd.x; d[g*4+1] = dd.y; d[g*4+2] = dd.z; d[g*4+3] = dd.w;
        }
        #pragma unroll
        for (int g = 0; g < 8; ++g) {
            float4 ee = *(const float4*)&e_sh[g * 4];
            if (g*4+0 < 31) e2[g*4+0] = fmaxf(ee.x * ee.x, 1e-28f);
            if (g*4+1 < 31) e2[g*4+1] = fmaxf(ee.y * ee.y, 1e-28f);
            if (g*4+2 < 31) e2[g*4+2] = fmaxf(ee.z * ee.z, 1e-28f);
            if (g*4+3 < 31) e2[g*4+3] = fmaxf(ee.w * ee.w, 1e-28f);
        }

        // ---- Sturm bisection: lane j isolates the j-th smallest eigenvalue ----
        #pragma unroll 1
        for (int it = 0; it < BITERS; ++it) {
            float mid = 0.5f * (lo + hi);
            float q   = d[0] - mid;
            int   c   = __float_as_int(q) >> 31;      // -1 per negative pivot
            #pragma unroll
            for (int i = 1; i < 32; ++i) {
                q  = fmaf(-e2[i - 1], frcp(q), d[i] - mid);
                c += __float_as_int(q) >> 31;
            }
            bool up = (c + lane >= 0);                // count(<mid) <= lane
            lo = up ? mid : lo;
            hi = up ? hi  : mid;
        }
        float lam = fmaxf(0.5f * (lo + hi), 1e-20f);
        float lg  = __logf(lam);
        contrib   = fsqrt_ap(warp_sum(lg * lg));
    }

    // ---- block reduce + last-block finalize ----
    if (lane == 0) wsum[wid] = contrib;
    __syncthreads();
    if (threadIdx.x == 0) {
        double s = ((double)wsum[0] + (double)wsum[1])
                 + ((double)wsum[2] + (double)wsum[3]);
        atomicAdd(&g_acc, s);
        __threadfence();
        unsigned t = atomicAdd(&g_cnt, 1u);
        if (t == gridDim.x - 1) {
            __threadfence();
            out[0] = (float)(g_acc / (double)B);
            g_acc = 0.0;
            g_cnt = 0u;
        }
    }
}

extern "C" void kernel_launch(void* const* d_in, const int* in_sizes, int n_in,
                              void* d_out, int out_size) {
    const float* x = (const float*)d_in[0];
    const float* y = (const float*)d_in[1];
    int B = in_sizes[0] / 1024;
    float* out = (float*)d_out;

    int blocks = (B + NW - 1) / NW;
    rdl_main<<<blocks, NW * 32>>>(x, y, out, B);
}

// round 10
// speedup vs baseline: 1.4750x; 1.0389x over previous
#include <cuda_runtime.h>
#include <cuda_bf16.h>
#include <math.h>

#define FULLMASK 0xFFFFFFFFu
#define NW 4              // warps per block, one matrix per warp
#define BITERS 8          // bisection iterations (err ~8e-5 << 1e-3 threshold)

// Compiler-only ordering fence for same-warp cross-lane smem traffic
// (all STS->LDS pairs sit in converged control flow).
#define WFENCE() asm volatile("" ::: "memory")

typedef unsigned long long ull;

__device__ double g_acc = 0.0;
__device__ unsigned int g_cnt = 0;

// packed-triangular row offset: float4-aligned, gap(i) >= i+1
__host__ __device__ constexpr int ro(int i) {
    return (i * (i + 1) / 2 + 3 * i + 3) & ~3;
}
#define LP_SIZE 640

__device__ __forceinline__ float warp_sum(float v) {
    v += __shfl_xor_sync(FULLMASK, v, 16);
    v += __shfl_xor_sync(FULLMASK, v, 8);
    v += __shfl_xor_sync(FULLMASK, v, 4);
    v += __shfl_xor_sync(FULLMASK, v, 2);
    v += __shfl_xor_sync(FULLMASK, v, 1);
    return v;
}

__device__ __forceinline__ float frcp(float x) {
    float r; asm("rcp.approx.f32 %0, %1;" : "=f"(r) : "f"(x)); return r;
}
__device__ __forceinline__ float fsqrt_ap(float x) {
    float r; asm("sqrt.approx.f32 %0, %1;" : "=f"(r) : "f"(x)); return r;
}

// ---- packed f32x2 helpers (FFMA2 path; ptxas never emits it from C++) ----
__device__ __forceinline__ ull pk2(float lo, float hi) {
    ull r; asm("mov.b64 %0, {%1, %2};" : "=l"(r) : "f"(lo), "f"(hi)); return r;
}
__device__ __forceinline__ void upk2(ull v, float& lo, float& hi) {
    asm("mov.b64 {%0, %1}, %2;" : "=f"(lo), "=f"(hi) : "l"(v));
}
__device__ __forceinline__ ull pfma(ull a, ull b, ull c) {
    ull r; asm("fma.rn.f32x2 %0, %1, %2, %3;" : "=l"(r) : "l"(a), "l"(b), "l"(c));
    return r;
}

__global__ __launch_bounds__(NW * 32, 6)
void rdl_main(const float* __restrict__ X, const float* __restrict__ Y,
              float* __restrict__ out, int B) {
    const int lane = threadIdx.x & 31;
    const int wid  = threadIdx.x >> 5;
    const int mat  = blockIdx.x * NW + wid;

    __shared__ float Lp[NW][LP_SIZE];  // packed lower-tri L; reused for d/e later
    __shared__ float Bs[NW][32][33];   // transpose buffer; rows 0 and 4 reused u/w
    __shared__ float wsum[NW];

    float* lp = Lp[wid];
    float contrib = 0.0f;

    if (mat < B) {                     // warp-uniform (mat is per-warp)
        const float* xb = X + (size_t)mat * 1024;
        const float* yb = Y + (size_t)mat * 1024;

        // ---- load Y column `lane` (== row, symmetric) ----
        float Lr[32];
        #pragma unroll
        for (int c = 0; c < 32; ++c) Lr[c] = yb[c * 32 + lane];

        const int rl = ((lane * (lane + 1)) / 2 + 3 * lane + 3) & ~3;

        // ---- Cholesky: row k of L broadcast from packed smem as float4 ----
        #pragma unroll
        for (int k = 0; k < 32; ++k) {
            WFENCE();
            float s0 = Lr[k], s1 = 0.f, s2 = 0.f, s3 = 0.f;
            #pragma unroll
            for (int g = 0; g * 4 < k; ++g) {
                float4 Lv = *(const float4*)(lp + ro(k) + g * 4);
                if (g*4+0 < k) s0 = fmaf(-Lr[g*4+0], Lv.x, s0);
                if (g*4+1 < k) s1 = fmaf(-Lr[g*4+1], Lv.y, s1);
                if (g*4+2 < k) s2 = fmaf(-Lr[g*4+2], Lv.z, s2);
                if (g*4+3 < k) s3 = fmaf(-Lr[g*4+3], Lv.w, s3);
            }
            float s   = (s0 + s1) + (s2 + s3);
            float skk = __shfl_sync(FULLMASK, s, k);
            float inv = rsqrtf(skk);
            float val = (lane == k) ? inv : s * inv;
            Lr[k] = val;
            if (lane >= k) lp[rl + k] = val;   // predicated packed column store
        }
        WFENCE();

        // ---- load X; forward solve L Z = X (thread = column, scalar) ----
        float z[32];
        #pragma unroll
        for (int c = 0; c < 32; ++c) z[c] = xb[c * 32 + lane];
        #pragma unroll
        for (int i = 0; i < 32; ++i) {
            float s = z[i];
            #pragma unroll
            for (int g = 0; g * 4 <= i; ++g) {
                float4 Lv = *(const float4*)(lp + ro(i) + g * 4);
                if (g*4+0 < i) s = fmaf(-Lv.x, z[g*4+0], s); else if (g*4+0 == i) s *= Lv.x;
                if (g*4+1 < i) s = fmaf(-Lv.y, z[g*4+1], s); else if (g*4+1 == i) s *= Lv.y;
                if (g*4+2 < i) s = fmaf(-Lv.z, z[g*4+2], s); else if (g*4+2 == i) s *= Lv.z;
                if (g*4+3 < i) s = fmaf(-Lv.w, z[g*4+3], s); else if (g*4+3 == i) s *= Lv.w;
            }
            z[i] = s;
        }

        // ---- transpose Z ----
        #pragma unroll
        for (int i = 0; i < 32; ++i) Bs[wid][lane][i] = z[i];
        WFENCE();

        // ---- forward solve L M = Z^T, producing PACKED m2 (column pairs).
        //      Inner products in f32x2; diag/tail via compile-time selects. ----
        ull m2[16];
        {
            float prev = 0.0f;                 // m[i-1], for odd-i tail
            #pragma unroll
            for (int i = 0; i < 32; ++i) {
                const int ieven = i & ~1;      // packed floats cover 0..ieven-1
                ull  a0 = 0ull, a1 = 0ull;
                float s = Bs[wid][i][lane];
                float inv = 0.0f;
                #pragma unroll
                for (int g = 0; g * 4 <= i; ++g) {
                    float4 Lv = *(const float4*)(lp + ro(i) + g * 4);
                    if (g*4+0 < ieven) a0 = pfma(pk2(Lv.x, Lv.y), m2[(g*4)>>1],   a0);
                    if (g*4+2 < ieven) a1 = pfma(pk2(Lv.z, Lv.w), m2[(g*4+2)>>1], a1);
                    if ((i & 1) && ((i - 1) >> 2) == g) {   // tail k = i-1 (odd i)
                        float Lt = ((i-1)&3)==0 ? Lv.x : ((i-1)&3)==1 ? Lv.y
                                 : ((i-1)&3)==2 ? Lv.z : Lv.w;
                        s = fmaf(-Lt, prev, s);
                    }
                    if ((i >> 2) == g)                       // diag (holds 1/L[i][i])
                        inv = (i&3)==0 ? Lv.x : (i&3)==1 ? Lv.y
                            : (i&3)==2 ? Lv.z : Lv.w;
                }
                float b0, b1, b2, b3;
                upk2(a0, b0, b1); upk2(a1, b2, b3);
                s = (s - ((b0 + b1) + (b2 + b3))) * inv;
                if (i & 1) m2[i >> 1] = pk2(prev, s);
                prev = s;
            }
        }
        WFENCE();   // Lp dead as L from here -> reuse for d / e

        float* d_sh = lp;        // [32] diag of T     (16B aligned)
        float* e_sh = lp + 32;   // [32] off-diag of T (16B aligned)

        // ---- Householder tridiag on packed m2; unnormalized reflector
        //      u = x - beta*e1, tau = 2/||u||^2. ----
        float* u_sh = &Bs[wid][0][0];   // 16B aligned, contiguous
        float* w_sh = &Bs[wid][4][0];   // 16B aligned, contiguous
        #pragma unroll
        for (int k = 0; k < 30; ++k) {
            float mlo, mhi; upk2(m2[k >> 1], mlo, mhi);
            float xk_raw = (k & 1) ? mhi : mlo;          // m[k] of this lane
            float xk     = (lane > k) ? xk_raw : 0.0f;
            float alpha  = __shfl_sync(FULLMASK, xk_raw, k + 1);
            float sigma  = warp_sum((lane > k + 1) ? xk * xk : 0.0f);

            float mu    = fsqrt_ap(fmaf(alpha, alpha, sigma));
            float beta  = (alpha >= 0.0f) ? -mu : mu;
            float ab    = alpha - beta;
            float tau   = __fdividef(2.0f, fmaf(ab, ab, sigma));  // 2/||u||^2
            float u     = (lane == k + 1) ? ab : xk;
            if (sigma <= 1e-12f) { beta = alpha; tau = 0.0f; u = 0.0f; }  // uniform
            if (lane == k) { d_sh[k] = xk_raw; e_sh[k] = beta; }  // row k final
            u_sh[lane] = u;
            WFENCE();

            // p = tau * A u, packed (u_j == 0 for j <= k -> over-range exact)
            ull acc0 = 0ull, acc1 = 0ull;
            #pragma unroll
            for (int g = (k + 1) & ~3; g < 32; g += 4) {
                float4 uu = *(const float4*)&u_sh[g];
                acc0 = pfma(m2[g >> 1],       pk2(uu.x, uu.y), acc0);
                acc1 = pfma(m2[(g >> 1) + 1], pk2(uu.z, uu.w), acc1);
            }
            float b0, b1, b2, b3;
            upk2(acc0, b0, b1); upk2(acc1, b2, b3);
            float p = ((b0 + b1) + (b2 + b3)) * tau;

            float dot = tau * warp_sum(p * u);
            float w   = fmaf(-0.5f * dot, u, p);
            w_sh[lane] = w;
            WFENCE();

            // trailing update packed: A <- A - u w^T - w u^T
            // (cols <= k in range: u_j = 0, w_j = 0 for j<k frozen; j=k term is
            //  the exact annihilation update -> all harmless/correct)
            ull nu2 = pk2(-u, -u), nw2 = pk2(-w, -w);
            #pragma unroll
            for (int g = (k + 1) & ~3; g < 32; g += 4) {
                float4 uu = *(const float4*)&u_sh[g];
                float4 ww = *(const float4*)&w_sh[g];
                int t = g >> 1;
                m2[t]   = pfma(nu2, pk2(ww.x, ww.y), pfma(nw2, pk2(uu.x, uu.y), m2[t]));
                m2[t+1] = pfma(nu2, pk2(ww.z, ww.w), pfma(nw2, pk2(uu.z, uu.w), m2[t+1]));
            }
        }
        {
            float mlo, mhi; upk2(m2[15], mlo, mhi);      // {m[30], m[31]}
            if (lane == 30) { d_sh[30] = mlo; e_sh[30] = mhi; }  // e[30]=M[31][30]
            if (lane == 31) { d_sh[31] = mhi; e_sh[31] = 0.0f; }
        }
        WFENCE();

        // ---- Gershgorin: per-lane row radius, 10-shfl min/max reduce ----
        float d_l = d_sh[lane];
        float ev  = (lane < 31) ? e_sh[lane] : 0.f;
        float em  = (lane > 0)  ? e_sh[lane - 1] : 0.f;
        float r   = fabsf(em) + fabsf(ev);
        float gl  = d_l - r, gh = d_l + r;
        #pragma unroll
        for (int o = 16; o > 0; o >>= 1) {
            gl = fminf(gl, __shfl_xor_sync(FULLMASK, gl, o));
            gh = fmaxf(gh, __shfl_xor_sync(FULLMASK, gh, o));
        }
        float span = gh - gl;
        float lo = gl - 1e-4f * span - 1e-6f;
        float hi = gh + 1e-4f * span + 1e-6f;

        // ---- pull T into registers via one-time float4 broadcasts ----
        float d[32], e2[31];
        #pragma unroll
        for (int g = 0; g < 8; ++g) {
            float4 dd = *(const float4*)&d_sh[g * 4];
            d[g*4+0] = dd.x; d[g*4+1] = dd.y; d[g*4+2] = dd.z; d[g*4+3] = dd.w;
        }
        #pragma unroll
        for (int g = 0; g < 8; ++g) {
            float4 ee = *(const float4*)&e_sh[g * 4];
            if (g*4+0 < 31) e2[g*4+0] = fmaxf(ee.x * ee.x, 1e-28f);
            if (g*4+1 < 31) e2[g*4+1] = fmaxf(ee.y * ee.y, 1e-28f);
            if (g*4+2 < 31) e2[g*4+2] = fmaxf(ee.z * ee.z, 1e-28f);
            if (g*4+3 < 31) e2[g*4+3] = fmaxf(ee.w * ee.w, 1e-28f);
        }

        // ---- Sturm bisection: lane j isolates the j-th smallest eigenvalue ----
        #pragma unroll 1
        for (int it = 0; it < BITERS; ++it) {
            float mid = 0.5f * (lo + hi);
            float q   = d[0] - mid;
            int   c   = __float_as_int(q) >> 31;      // -1 per negative pivot
            #pragma unroll
            for (int i = 1; i < 32; ++i) {
                q  = fmaf(-e2[i - 1], frcp(q), d[i] - mid);
                c += __float_as_int(q) >> 31;
            }
            bool up = (c + lane >= 0);                // count(<mid) <= lane
            lo = up ? mid : lo;
            hi = up ? hi  : mid;
        }
        float lam = fmaxf(0.5f * (lo + hi), 1e-20f);
        float lg  = __logf(lam);
        contrib   = fsqrt_ap(warp_sum(lg * lg));
    }

    // ---- block reduce + last-block finalize ----
    if (lane == 0) wsum[wid] = contrib;
    __syncthreads();
    if (threadIdx.x == 0) {
        double s = ((double)wsum[0] + (double)wsum[1])
                 + ((double)wsum[2] + (double)wsum[3]);
        atomicAdd(&g_acc, s);
        __threadfence();
        unsigned t = atomicAdd(&g_cnt, 1u);
        if (t == gridDim.x - 1) {
            __threadfence();
            out[0] = (float)(g_acc / (double)B);
            g_acc = 0.0;
            g_cnt = 0u;
        }
    }
}

extern "C" void kernel_launch(void* const* d_in, const int* in_sizes, int n_in,
                              void* d_out, int out_size) {
    const float* x = (const float*)d_in[0];
    const float* y = (const float*)d_in[1];
    int B = in_sizes[0] / 1024;
    float* out = (float*)d_out;

    int blocks = (B + NW - 1) / NW;
    rdl_main<<<blocks, NW * 32>>>(x, y, out, B);
}